// round 2
// baseline (speedup 1.0000x reference)
#include <cuda_runtime.h>
#include <cstdint>

// Fixed problem shape (SequenceExtract_77953656423028): B=8, S=4096, H=1024
#define BDIM 8
#define SDIM 4096
#define HDIM 1024

// Scratch (no allocations allowed)
__device__ int g_tokpos[BDIM * SDIM];            // compacted original positions per row
__device__ int g_nkeep[BDIM];                    // #kept tokens per row
__device__ int g_nzero[BDIM];                    // #kept tokens with attention_mask == 0
__device__ unsigned long long g_keys[BDIM * SDIM]; // sort keys at original positions (0 = not kept)

// ---------------------------------------------------------------------------
// K0: new_ret = hidden_states (exact copy), vectorized
// ---------------------------------------------------------------------------
__global__ void copy_kernel(const float4* __restrict__ src, float4* __restrict__ dst, int n4) {
    int i = blockIdx.x * blockDim.x + threadIdx.x;
    int stride = gridDim.x * blockDim.x;
    for (; i < n4; i += stride) dst[i] = src[i];
}

// ---------------------------------------------------------------------------
// K1: per-row compaction of kept tokens + counts + zero keys
// one block (1024 threads) per batch row, 4 positions per thread
// ---------------------------------------------------------------------------
__global__ void compact_kernel(const float* __restrict__ pmask,
                               const float* __restrict__ amask) {
    int b = blockIdx.x;
    int t = threadIdx.x;
    __shared__ int cnt[1024];
    __shared__ int cntz_s[1024];
    int base = b * SDIM;

    int flags = 0, local = 0, localz = 0;
#pragma unroll
    for (int r = 0; r < 4; r++) {
        int p = t * 4 + r;
        bool k = pmask[base + p] > 0.5f;
        flags |= (int)k << r;
        local += k;
        if (k && amask[base + p] == 0.0f) localz++;
        g_keys[base + p] = 0ull;
    }
    cnt[t] = local;
    cntz_s[t] = localz;
    __syncthreads();
    // inclusive scan over thread counts (Hillis-Steele, race-safe via staged sync)
    for (int off = 1; off < 1024; off <<= 1) {
        int v = (t >= off) ? cnt[t - off] : 0;
        int vz = (t >= off) ? cntz_s[t - off] : 0;
        __syncthreads();
        cnt[t] += v;
        cntz_s[t] += vz;
        __syncthreads();
    }
    int offset = cnt[t] - local;
#pragma unroll
    for (int r = 0; r < 4; r++) {
        if ((flags >> r) & 1) {
            g_tokpos[base + offset] = t * 4 + r;
            offset++;
        }
    }
    if (t == 1023) {
        g_nkeep[b] = cnt[1023];
        g_nzero[b] = cntz_s[1023];
    }
}

// ---------------------------------------------------------------------------
// K2: fp32 GEMM (kept-rows x W) with row-max epilogue -> sort keys
// block = 256 threads, tile BM=64 tokens x BN=64 cols, BK=16
// ---------------------------------------------------------------------------
__global__ void __launch_bounds__(256, 4)
score_gemm(const float* __restrict__ hid, const float* __restrict__ W,
           const float* __restrict__ bias, const float* __restrict__ amask) {
    int b = blockIdx.y;
    int nk = g_nkeep[b];
    int m0 = blockIdx.x * 64;
    if (m0 >= nk) return;

    __shared__ float As[16][64];   // [k][m] (transposed)
    __shared__ float Bs[16][64];   // [k][n]
    __shared__ float red[64][17];  // row-max cross-thread reduce

    int tid = threadIdx.x;
    int tx = tid & 15;        // col group
    int ty = tid >> 4;        // row group
    int arow = tid >> 2;      // A-load row (0..63)
    int akk = (tid & 3) * 4;  // A-load k offset

    int rowbase = b * SDIM;
    int tp = (m0 + arow < nk) ? g_tokpos[rowbase + m0 + arow] : g_tokpos[rowbase];
    const float* aRow = hid + ((size_t)rowbase + tp) * HDIM + akk;
    const float* bBase = W + (size_t)(tid >> 4) * HDIM + (tid & 15) * 4;

    float rmax[4] = {-3.4e38f, -3.4e38f, -3.4e38f, -3.4e38f};

    for (int n0 = 0; n0 < HDIM; n0 += 64) {
        float acc[4][4];
#pragma unroll
        for (int r = 0; r < 4; r++)
#pragma unroll
            for (int c = 0; c < 4; c++) acc[r][c] = 0.0f;

        for (int k0 = 0; k0 < HDIM; k0 += 16) {
            float4 av = *(const float4*)(aRow + k0);
            As[akk + 0][arow] = av.x;
            As[akk + 1][arow] = av.y;
            As[akk + 2][arow] = av.z;
            As[akk + 3][arow] = av.w;
            float4 bv = *(const float4*)(bBase + (size_t)k0 * HDIM + n0);
            *(float4*)&Bs[tid >> 4][(tid & 15) * 4] = bv;
            __syncthreads();
#pragma unroll
            for (int kk = 0; kk < 16; kk++) {
                float4 a = *(float4*)&As[kk][ty * 4];
                float4 bb = *(float4*)&Bs[kk][tx * 4];
                float ar[4] = {a.x, a.y, a.z, a.w};
                float bc[4] = {bb.x, bb.y, bb.z, bb.w};
#pragma unroll
                for (int r = 0; r < 4; r++)
#pragma unroll
                    for (int c = 0; c < 4; c++) acc[r][c] += ar[r] * bc[c];
            }
            __syncthreads();
        }
        float4 bi = *(const float4*)(bias + n0 + tx * 4);
        float bc[4] = {bi.x, bi.y, bi.z, bi.w};
#pragma unroll
        for (int r = 0; r < 4; r++)
#pragma unroll
            for (int c = 0; c < 4; c++)
                rmax[r] = fmaxf(rmax[r], acc[r][c] + bc[c]);
    }

#pragma unroll
    for (int r = 0; r < 4; r++) red[ty * 4 + r][tx] = rmax[r];
    __syncthreads();

    if (tid < 64) {
        int m = m0 + tid;
        if (m < nk) {
            float s = red[tid][0];
#pragma unroll
            for (int i = 1; i < 16; i++) s = fmaxf(s, red[tid][i]);
            int pos = g_tokpos[rowbase + m];
            float a = amask[rowbase + pos];
            // reference: scores = max + a*100 ; then s = scores + a
            s = s + a * 100.0f + a;
            unsigned u = __float_as_uint(s);
            u = (u & 0x80000000u) ? ~u : (u | 0x80000000u);
            unsigned long long key =
                ((unsigned long long)u << 32) | (unsigned long long)(0xFFFFFFFFu - (unsigned)pos);
            g_keys[rowbase + pos] = key;
        }
    }
}

// ---------------------------------------------------------------------------
// K3: per-row top-T selection via bitonic sort of 4096 64-bit keys, write mask
// one block (1024 threads) per batch row
// ---------------------------------------------------------------------------
__global__ void select_kernel(float* __restrict__ outmask) {
    int b = blockIdx.x;
    int t = threadIdx.x;
    __shared__ unsigned long long s[SDIM];
    int base = b * SDIM;

    for (int i = t; i < SDIM; i += 1024) s[i] = g_keys[base + i];
    __syncthreads();

    // bitonic sort ascending
    for (int k = 2; k <= SDIM; k <<= 1) {
        for (int j = k >> 1; j > 0; j >>= 1) {
            for (int i = t; i < SDIM; i += 1024) {
                int ixj = i ^ j;
                if (ixj > i) {
                    unsigned long long A = s[i], B = s[ixj];
                    bool up = ((i & k) == 0);
                    if ((A > B) == up) { s[i] = B; s[ixj] = A; }
                }
            }
            __syncthreads();
        }
    }

    int cz = g_nzero[b];
    int T = (int)((float)cz * 0.8f);   // matches jnp f32 truncation
    if (T < 1) T = 1;
    unsigned long long thresh = s[SDIM - T];

    for (int i = t; i < SDIM; i += 1024)
        outmask[base + i] = (g_keys[base + i] >= thresh) ? 1.0f : 0.0f;
}

// ---------------------------------------------------------------------------
extern "C" void kernel_launch(void* const* d_in, const int* in_sizes, int n_in,
                              void* d_out, int out_size) {
    const float* hidden = (const float*)d_in[0];
    const float* amask  = (const float*)d_in[1];
    const float* pmask  = (const float*)d_in[2];
    const float* W      = (const float*)d_in[3];
    const float* bias   = (const float*)d_in[4];
    float* out = (float*)d_out;

    const int nh = BDIM * SDIM * HDIM;      // 33,554,432
    float* out_ret  = out;                  // [B,S,H]
    float* out_mask = out + nh;             // [B,S]

    // K0: new_ret = hidden_states
    int n4 = nh / 4;
    copy_kernel<<<n4 / 256, 256>>>((const float4*)hidden, (float4*)out_ret, n4);

    // K1: compaction + counts + key reset
    compact_kernel<<<BDIM, 1024>>>(pmask, amask);

    // K2: scores for kept tokens
    dim3 g2(SDIM / 64, BDIM);
    score_gemm<<<g2, 256>>>(hidden, W, bias, amask);

    // K3: top-T selection per row -> new_mask
    select_kernel<<<BDIM, 1024>>>(out_mask);
}

// round 5
// speedup vs baseline: 2.8792x; 2.8792x over previous
#include <cuda_runtime.h>
#include <cuda_fp16.h>
#include <cstdint>

// Fixed shape: B=8, S=4096, H=1024
#define BDIM 8
#define SDIM 4096
#define HDIM 1024

// GEMM tiling
#define BM 128
#define BN 128
#define BKH 32                 // k-chunk (fp16 elems) per stage
#define KT (HDIM / BKH)        // 32 iterations
#define ROWB 80                // smem row stride bytes (32 halves + 16B pad)
#define PLANE (BM * ROWB)      // 10240 bytes
#define STAGE_BYTES (4 * PLANE) // Ah, Al, Bh, Bl = 40960
#define SMEM_DYN (3 * STAGE_BYTES + 512)

// ---------------- device scratch (no allocations allowed) ----------------
__device__ int g_tokpos[BDIM * SDIM];
__device__ int g_nkeep[BDIM];
__device__ int g_nzero[BDIM];
__device__ unsigned g_score[BDIM * SDIM];           // monotone-mapped row max
__device__ __half g_Ahi[BDIM * SDIM * HDIM];        // compacted kept rows, hi
__device__ __half g_Alo[BDIM * SDIM * HDIM];        // compacted kept rows, lo
__device__ __half g_Bhi[HDIM * HDIM];               // W^T [n][k], hi
__device__ __half g_Blo[HDIM * HDIM];               // W^T [n][k], lo

// ---------------- asm helpers (sm_103-base-safe only) ----------------
__device__ __forceinline__ uint32_t smem_u32(const void* p) {
    uint32_t a;
    asm("{ .reg .u64 t; cvta.to.shared.u64 t, %1; cvt.u32.u64 %0, t; }" : "=r"(a) : "l"(p));
    return a;
}
#define CP16(d, s) asm volatile("cp.async.cg.shared.global [%0], [%1], 16;" :: "r"(d), "l"(s))
#define CP_COMMIT() asm volatile("cp.async.commit_group;" ::: "memory")
#define CP_WAIT2() asm volatile("cp.async.wait_group 2;" ::: "memory")

#define LDX4(R, addr) \
    asm volatile("ldmatrix.sync.aligned.m8n8.x4.shared.b16 {%0,%1,%2,%3}, [%4];" \
        : "=r"((R)[0]), "=r"((R)[1]), "=r"((R)[2]), "=r"((R)[3]) : "r"(addr))

#define MMA16816(C, A, B0, B1) \
    asm volatile("mma.sync.aligned.m16n8k16.row.col.f32.f16.f16.f32 " \
        "{%0,%1,%2,%3}, {%4,%5,%6,%7}, {%8,%9}, {%0,%1,%2,%3};" \
        : "+f"((C)[0]), "+f"((C)[1]), "+f"((C)[2]), "+f"((C)[3]) \
        : "r"((A)[0]), "r"((A)[1]), "r"((A)[2]), "r"((A)[3]), "r"(B0), "r"(B1))

__device__ __forceinline__ unsigned mono(float s) {
    unsigned u = __float_as_uint(s);
    return (u & 0x80000000u) ? ~u : (u | 0x80000000u);
}

// ---------------------------------------------------------------------------
// K0: new_ret = hidden_states (exact copy)
// ---------------------------------------------------------------------------
__global__ void copy_kernel(const float4* __restrict__ src, float4* __restrict__ dst, int n4) {
    int i = blockIdx.x * blockDim.x + threadIdx.x;
    int stride = gridDim.x * blockDim.x;
    for (; i < n4; i += stride) dst[i] = src[i];
}

// ---------------------------------------------------------------------------
// K1: per-row compaction + counts + score reset (validated in R1)
// ---------------------------------------------------------------------------
__global__ void compact_kernel(const float* __restrict__ pmask,
                               const float* __restrict__ amask) {
    int b = blockIdx.x;
    int t = threadIdx.x;
    __shared__ int cnt[1024];
    __shared__ int cntz_s[1024];
    int base = b * SDIM;

    int flags = 0, local = 0, localz = 0;
#pragma unroll
    for (int r = 0; r < 4; r++) {
        int p = t * 4 + r;
        bool k = pmask[base + p] > 0.5f;
        flags |= (int)k << r;
        local += k;
        if (k && amask[base + p] == 0.0f) localz++;
        g_score[base + p] = 0u;
    }
    cnt[t] = local;
    cntz_s[t] = localz;
    __syncthreads();
    for (int off = 1; off < 1024; off <<= 1) {
        int v = (t >= off) ? cnt[t - off] : 0;
        int vz = (t >= off) ? cntz_s[t - off] : 0;
        __syncthreads();
        cnt[t] += v;
        cntz_s[t] += vz;
        __syncthreads();
    }
    int offset = cnt[t] - local;
#pragma unroll
    for (int r = 0; r < 4; r++) {
        if ((flags >> r) & 1) {
            g_tokpos[base + offset] = t * 4 + r;
            offset++;
        }
    }
    if (t == 1023) {
        g_nkeep[b] = cnt[1023];
        g_nzero[b] = cntz_s[1023];
    }
}

// ---------------------------------------------------------------------------
// K_prepW: W[k][n] fp32 -> W^T[n][k] fp16 hi/lo (tiled transpose)
// grid (32,32), block (32,8)
// ---------------------------------------------------------------------------
__global__ void prep_w(const float* __restrict__ W) {
    __shared__ float t[32][33];
    int n0 = blockIdx.x * 32, k0 = blockIdx.y * 32;
    int tx = threadIdx.x, ty = threadIdx.y;
#pragma unroll
    for (int r = 0; r < 4; r++)
        t[ty + r * 8][tx] = W[(size_t)(k0 + ty + r * 8) * HDIM + n0 + tx];
    __syncthreads();
#pragma unroll
    for (int r = 0; r < 4; r++) {
        int n = ty + r * 8;
        float x = t[tx][n];
        __half h = __float2half_rn(x);
        __half l = __float2half_rn(x - __half2float(h));
        size_t d = (size_t)(n0 + n) * HDIM + k0 + tx;
        g_Bhi[d] = h;
        g_Blo[d] = l;
    }
}

// ---------------------------------------------------------------------------
// K_prepA: gather kept rows, split fp32 -> fp16 hi/lo, store compacted
// grid (SDIM, BDIM), block 128
// ---------------------------------------------------------------------------
__global__ void prep_a(const float* __restrict__ hid) {
    int slot = blockIdx.x, b = blockIdx.y;
    if (slot >= g_nkeep[b]) return;
    int tp = g_tokpos[b * SDIM + slot];
    const float4* src = (const float4*)(hid + ((size_t)(b * SDIM + tp)) * HDIM);
    size_t dbase = (size_t)(b * SDIM + slot) * HDIM;
#pragma unroll
    for (int i = 0; i < 2; i++) {
        int e4 = threadIdx.x + i * 128;
        float4 v = src[e4];
        float f[4] = {v.x, v.y, v.z, v.w};
        __half h[4], l[4];
#pragma unroll
        for (int q = 0; q < 4; q++) {
            h[q] = __float2half_rn(f[q]);
            l[q] = __float2half_rn(f[q] - __half2float(h[q]));
        }
        uint2 uh, ul;
        uh.x = (__half_as_ushort(h[1]) << 16) | __half_as_ushort(h[0]);
        uh.y = (__half_as_ushort(h[3]) << 16) | __half_as_ushort(h[2]);
        ul.x = (__half_as_ushort(l[1]) << 16) | __half_as_ushort(l[0]);
        ul.y = (__half_as_ushort(l[3]) << 16) | __half_as_ushort(l[2]);
        *(uint2*)(g_Ahi + dbase + e4 * 4) = uh;
        *(uint2*)(g_Alo + dbase + e4 * 4) = ul;
    }
}

// ---------------------------------------------------------------------------
// K2: split-fp16 mma.sync GEMM (hh + lh + hl), row-max epilogue -> atomicMax
// grid (32, 8, BDIM), block 256 (8 warps, 2x4 warp grid, warp tile 64x32)
// ---------------------------------------------------------------------------
__global__ void __launch_bounds__(256, 1)
score_gemm(const float* __restrict__ bias) {
    int b = blockIdx.z;
    int nk = g_nkeep[b];
    int m0 = blockIdx.x * BM;
    if (m0 >= nk) return;
    int n0 = blockIdx.y * BN;

    extern __shared__ __align__(128) char sm[];
    uint32_t sb = smem_u32(sm);
    float* biasS = (float*)(sm + 3 * STAGE_BYTES);

    int tid = threadIdx.x, wid = tid >> 5, lane = tid & 31;
    if (tid < BN) biasS[tid] = bias[n0 + tid];

    const __half* gah = g_Ahi + (size_t)(b * SDIM + m0) * HDIM;
    const __half* gal = g_Alo + (size_t)(b * SDIM + m0) * HDIM;
    const __half* gbh = g_Bhi + (size_t)n0 * HDIM;
    const __half* gbl = g_Blo + (size_t)n0 * HDIM;

#define LOAD_STAGE(s, k0)                                                     \
    do {                                                                      \
        uint32_t st_ = sb + (s) * STAGE_BYTES;                                \
        _Pragma("unroll")                                                     \
        for (int i_ = 0; i_ < 2; i_++) {                                      \
            int cid_ = tid + i_ * 256;                                        \
            int r_ = cid_ >> 2, c_ = cid_ & 3;                                \
            uint32_t so_ = (uint32_t)(r_ * ROWB + c_ * 16);                   \
            size_t go_ = (size_t)r_ * HDIM + (k0) + c_ * 8;                   \
            CP16(st_ + so_,             gah + go_);                           \
            CP16(st_ + PLANE + so_,     gal + go_);                           \
            CP16(st_ + 2 * PLANE + so_, gbh + go_);                           \
            CP16(st_ + 3 * PLANE + so_, gbl + go_);                           \
        }                                                                     \
    } while (0)

    LOAD_STAGE(0, 0);
    CP_COMMIT();
    LOAD_STAGE(1, BKH);
    CP_COMMIT();

    int wm = wid >> 2, wn = wid & 3;
    float acc[4][4][4];
#pragma unroll
    for (int mt = 0; mt < 4; mt++)
#pragma unroll
        for (int nt = 0; nt < 4; nt++)
#pragma unroll
            for (int e = 0; e < 4; e++) acc[mt][nt][e] = 0.0f;

    uint32_t arow = (uint32_t)(wm * 64 + (lane & 15));
    uint32_t brow = (uint32_t)(wn * 32 + (lane & 15));
    uint32_t kcol = (uint32_t)((lane >> 4) * 16);

    for (int kt = 0; kt < KT; kt++) {
        if (kt + 2 < KT) LOAD_STAGE((kt + 2) % 3, (kt + 2) * BKH);
        CP_COMMIT();
        CP_WAIT2();
        __syncthreads();

        uint32_t st = sb + (kt % 3) * STAGE_BYTES;
#pragma unroll
        for (int ks = 0; ks < 2; ks++) {
            uint32_t koff = (uint32_t)(ks * 32) + kcol;
            uint32_t ah[4][4], al[4][4], bh[2][4], bl[2][4];
#pragma unroll
            for (int mt = 0; mt < 4; mt++) {
                uint32_t ra = st + (arow + mt * 16) * ROWB + koff;
                LDX4(ah[mt], ra);
                LDX4(al[mt], ra + PLANE);
            }
#pragma unroll
            for (int g = 0; g < 2; g++) {
                uint32_t rb = st + 2 * PLANE + (brow + g * 16) * ROWB + koff;
                LDX4(bh[g], rb);
                LDX4(bl[g], rb + PLANE);
            }
#pragma unroll
            for (int mt = 0; mt < 4; mt++)
#pragma unroll
                for (int nt = 0; nt < 4; nt++) {
                    int g = nt >> 1, s2 = nt & 1;
                    MMA16816(acc[mt][nt], ah[mt], bh[g][s2], bh[g][s2 + 2]);
                    MMA16816(acc[mt][nt], al[mt], bh[g][s2], bh[g][s2 + 2]);
                    MMA16816(acc[mt][nt], ah[mt], bl[g][s2], bl[g][s2 + 2]);
                }
        }
        __syncthreads();
    }

    // ---- epilogue: bias add + row max + lane reduce + atomicMax ----
    float rmax[4][2];
#pragma unroll
    for (int mt = 0; mt < 4; mt++) { rmax[mt][0] = -3.4e38f; rmax[mt][1] = -3.4e38f; }
#pragma unroll
    for (int mt = 0; mt < 4; mt++)
#pragma unroll
        for (int nt = 0; nt < 4; nt++) {
            int cb = wn * 32 + nt * 8 + (lane & 3) * 2;
            float b0 = biasS[cb], b1 = biasS[cb + 1];
            rmax[mt][0] = fmaxf(rmax[mt][0], fmaxf(acc[mt][nt][0] + b0, acc[mt][nt][1] + b1));
            rmax[mt][1] = fmaxf(rmax[mt][1], fmaxf(acc[mt][nt][2] + b0, acc[mt][nt][3] + b1));
        }
#pragma unroll
    for (int off = 1; off <= 2; off <<= 1)
#pragma unroll
        for (int mt = 0; mt < 4; mt++) {
            rmax[mt][0] = fmaxf(rmax[mt][0], __shfl_xor_sync(0xFFFFFFFFu, rmax[mt][0], off));
            rmax[mt][1] = fmaxf(rmax[mt][1], __shfl_xor_sync(0xFFFFFFFFu, rmax[mt][1], off));
        }
    if ((lane & 3) == 0) {
#pragma unroll
        for (int mt = 0; mt < 4; mt++)
#pragma unroll
            for (int h2 = 0; h2 < 2; h2++) {
                int m = m0 + wm * 64 + mt * 16 + (lane >> 2) + h2 * 8;
                if (m < nk) {
                    int pos = g_tokpos[b * SDIM + m];
                    atomicMax(&g_score[b * SDIM + pos], mono(rmax[mt][h2]));
                }
            }
    }
#undef LOAD_STAGE
}

// ---------------------------------------------------------------------------
// K3: per-row top-T via bitonic sort of rebuilt keys -> new_mask
// ---------------------------------------------------------------------------
__device__ __forceinline__ unsigned long long make_key(int base, int i,
                                                       const float* pmask,
                                                       const float* amask) {
    if (pmask[base + i] <= 0.5f) return 0ull;
    unsigned u = g_score[base + i];
    unsigned bits = (u & 0x80000000u) ? (u & 0x7FFFFFFFu) : ~u;   // un-map
    float sc = __uint_as_float(bits);
    float a = amask[base + i];
    sc = sc + a * 100.0f + a;
    unsigned v = __float_as_uint(sc);
    v = (v & 0x80000000u) ? ~v : (v | 0x80000000u);               // re-map
    return ((unsigned long long)v << 32) | (unsigned long long)(0xFFFFFFFFu - (unsigned)i);
}

__global__ void select_kernel(const float* __restrict__ pmask,
                              const float* __restrict__ amask,
                              float* __restrict__ outmask) {
    int b = blockIdx.x;
    int t = threadIdx.x;
    __shared__ unsigned long long s[SDIM];
    int base = b * SDIM;

    for (int i = t; i < SDIM; i += 1024) s[i] = make_key(base, i, pmask, amask);
    __syncthreads();

    for (int k = 2; k <= SDIM; k <<= 1) {
        for (int j = k >> 1; j > 0; j >>= 1) {
            for (int i = t; i < SDIM; i += 1024) {
                int ixj = i ^ j;
                if (ixj > i) {
                    unsigned long long A = s[i], B = s[ixj];
                    bool up = ((i & k) == 0);
                    if ((A > B) == up) { s[i] = B; s[ixj] = A; }
                }
            }
            __syncthreads();
        }
    }

    int cz = g_nzero[b];
    int T = (int)((float)cz * 0.8f);
    if (T < 1) T = 1;
    unsigned long long thresh = s[SDIM - T];

    for (int i = t; i < SDIM; i += 1024)
        outmask[base + i] = (make_key(base, i, pmask, amask) >= thresh) ? 1.0f : 0.0f;
}

// ---------------------------------------------------------------------------
extern "C" void kernel_launch(void* const* d_in, const int* in_sizes, int n_in,
                              void* d_out, int out_size) {
    const float* hidden = (const float*)d_in[0];
    const float* amask  = (const float*)d_in[1];
    const float* pmask  = (const float*)d_in[2];
    const float* W      = (const float*)d_in[3];
    const float* bias   = (const float*)d_in[4];
    float* out = (float*)d_out;

    const int nh = BDIM * SDIM * HDIM;
    float* out_ret  = out;
    float* out_mask = out + nh;

    cudaFuncSetAttribute(score_gemm, cudaFuncAttributeMaxDynamicSharedMemorySize, SMEM_DYN);

    // compaction + counts + score reset (needed by prep_a)
    compact_kernel<<<BDIM, 1024>>>(pmask, amask);

    // W -> [n][k] fp16 hi/lo
    prep_w<<<dim3(32, 32), dim3(32, 8)>>>(W);

    // kept rows -> compacted fp16 hi/lo planes
    prep_a<<<dim3(SDIM, BDIM), 128>>>(hidden);

    // new_ret = hidden_states
    copy_kernel<<<2048, 256>>>((const float4*)hidden, (float4*)out_ret, nh / 4);

    // split-fp16 tensor-core score GEMM
    score_gemm<<<dim3(SDIM / BM, HDIM / BN, BDIM), 256, SMEM_DYN>>>(bias);

    // top-T selection per row
    select_kernel<<<BDIM, 1024>>>(pmask, amask, out_mask);
}

// round 6
// speedup vs baseline: 3.3847x; 1.1756x over previous
#include <cuda_runtime.h>
#include <cuda_fp16.h>
#include <cstdint>

// Fixed shape: B=8, S=4096, H=1024
#define BDIM 8
#define SDIM 4096
#define HDIM 1024

// GEMM tiling
#define BM 128
#define BN 128
#define BKH 32                 // k-chunk (fp16 elems) per stage
#define KT (HDIM / BKH)        // 32 iterations
#define ROWB 80                // smem row stride bytes (32 halves + 16B pad)
#define PLANE (BM * ROWB)      // 10240 bytes
#define STAGE_BYTES (4 * PLANE) // Ah, Al, Bh, Bl = 40960
#define SMEM_DYN (2 * STAGE_BYTES + 512)   // 2 stages + bias -> 2 CTAs/SM

// ---------------- device scratch (no allocations allowed) ----------------
__device__ int g_tokpos[BDIM * SDIM];
__device__ int g_slot[BDIM * SDIM];                 // pos -> compacted slot (-1 if dropped)
__device__ int g_nkeep[BDIM];
__device__ int g_nzero[BDIM];
__device__ unsigned g_score[BDIM * SDIM];           // monotone-mapped row max
__device__ __half g_Ahi[BDIM * SDIM * HDIM];        // compacted kept rows, hi
__device__ __half g_Alo[BDIM * SDIM * HDIM];        // compacted kept rows, lo
__device__ __half g_Bhi[HDIM * HDIM];               // W^T [n][k], hi
__device__ __half g_Blo[HDIM * HDIM];               // W^T [n][k], lo

// ---------------- asm helpers (sm_103-base-safe only) ----------------
__device__ __forceinline__ uint32_t smem_u32(const void* p) {
    uint32_t a;
    asm("{ .reg .u64 t; cvta.to.shared.u64 t, %1; cvt.u32.u64 %0, t; }" : "=r"(a) : "l"(p));
    return a;
}
#define CP16(d, s) asm volatile("cp.async.cg.shared.global [%0], [%1], 16;" :: "r"(d), "l"(s))
#define CP_COMMIT() asm volatile("cp.async.commit_group;" ::: "memory")
#define CP_WAIT1() asm volatile("cp.async.wait_group 1;" ::: "memory")

#define LDX4(R, addr) \
    asm volatile("ldmatrix.sync.aligned.m8n8.x4.shared.b16 {%0,%1,%2,%3}, [%4];" \
        : "=r"((R)[0]), "=r"((R)[1]), "=r"((R)[2]), "=r"((R)[3]) : "r"(addr))

#define MMA16816(C, A, B0, B1) \
    asm volatile("mma.sync.aligned.m16n8k16.row.col.f32.f16.f16.f32 " \
        "{%0,%1,%2,%3}, {%4,%5,%6,%7}, {%8,%9}, {%0,%1,%2,%3};" \
        : "+f"((C)[0]), "+f"((C)[1]), "+f"((C)[2]), "+f"((C)[3]) \
        : "r"((A)[0]), "r"((A)[1]), "r"((A)[2]), "r"((A)[3]), "r"(B0), "r"(B1))

__device__ __forceinline__ unsigned mono(float s) {
    unsigned u = __float_as_uint(s);
    return (u & 0x80000000u) ? ~u : (u | 0x80000000u);
}

// ---------------------------------------------------------------------------
// K1: per-row compaction + counts + score reset + inverse slot map
// ---------------------------------------------------------------------------
__global__ void compact_kernel(const float* __restrict__ pmask,
                               const float* __restrict__ amask) {
    int b = blockIdx.x;
    int t = threadIdx.x;
    __shared__ int cnt[1024];
    __shared__ int cntz_s[1024];
    int base = b * SDIM;

    int flags = 0, local = 0, localz = 0;
#pragma unroll
    for (int r = 0; r < 4; r++) {
        int p = t * 4 + r;
        bool k = pmask[base + p] > 0.5f;
        flags |= (int)k << r;
        local += k;
        if (k && amask[base + p] == 0.0f) localz++;
        g_score[base + p] = 0u;
        g_slot[base + p] = -1;
    }
    cnt[t] = local;
    cntz_s[t] = localz;
    __syncthreads();
    for (int off = 1; off < 1024; off <<= 1) {
        int v = (t >= off) ? cnt[t - off] : 0;
        int vz = (t >= off) ? cntz_s[t - off] : 0;
        __syncthreads();
        cnt[t] += v;
        cntz_s[t] += vz;
        __syncthreads();
    }
    int offset = cnt[t] - local;
#pragma unroll
    for (int r = 0; r < 4; r++) {
        if ((flags >> r) & 1) {
            g_tokpos[base + offset] = t * 4 + r;
            g_slot[base + t * 4 + r] = offset;
            offset++;
        }
    }
    if (t == 1023) {
        g_nkeep[b] = cnt[1023];
        g_nzero[b] = cntz_s[1023];
    }
}

// ---------------------------------------------------------------------------
// K_prepW: W[k][n] fp32 -> W^T[n][k] fp16 hi/lo (tiled transpose)
// ---------------------------------------------------------------------------
__global__ void prep_w(const float* __restrict__ W) {
    __shared__ float t[32][33];
    int n0 = blockIdx.x * 32, k0 = blockIdx.y * 32;
    int tx = threadIdx.x, ty = threadIdx.y;
#pragma unroll
    for (int r = 0; r < 4; r++)
        t[ty + r * 8][tx] = W[(size_t)(k0 + ty + r * 8) * HDIM + n0 + tx];
    __syncthreads();
#pragma unroll
    for (int r = 0; r < 4; r++) {
        int n = ty + r * 8;
        float x = t[tx][n];
        __half h = __float2half_rn(x);
        __half l = __float2half_rn(x - __half2float(h));
        size_t d = (size_t)(n0 + n) * HDIM + k0 + tx;
        g_Bhi[d] = h;
        g_Blo[d] = l;
    }
}

// ---------------------------------------------------------------------------
// K_prep_copy: single pass over hidden — copy to out_ret, and for kept rows
// also split fp32 -> fp16 hi/lo into compacted planes. grid 32768, block 128.
// ---------------------------------------------------------------------------
__global__ void prep_copy(const float4* __restrict__ hid, float4* __restrict__ out_ret) {
    int row = blockIdx.x;                       // b*SDIM + s
    const float4* src = hid + (size_t)row * (HDIM / 4);
    float4* dst = out_ret + (size_t)row * (HDIM / 4);
    int slot = g_slot[row];

    if (slot < 0) {
#pragma unroll
        for (int i = 0; i < 2; i++) {
            int e4 = threadIdx.x + i * 128;
            dst[e4] = src[e4];
        }
        return;
    }
    int b = row >> 12;
    size_t dbase = (size_t)((b << 12) + slot) * HDIM;
#pragma unroll
    for (int i = 0; i < 2; i++) {
        int e4 = threadIdx.x + i * 128;
        float4 v = src[e4];
        dst[e4] = v;
        float f[4] = {v.x, v.y, v.z, v.w};
        __half h[4], l[4];
#pragma unroll
        for (int q = 0; q < 4; q++) {
            h[q] = __float2half_rn(f[q]);
            l[q] = __float2half_rn(f[q] - __half2float(h[q]));
        }
        uint2 uh, ul;
        uh.x = ((unsigned)__half_as_ushort(h[1]) << 16) | __half_as_ushort(h[0]);
        uh.y = ((unsigned)__half_as_ushort(h[3]) << 16) | __half_as_ushort(h[2]);
        ul.x = ((unsigned)__half_as_ushort(l[1]) << 16) | __half_as_ushort(l[0]);
        ul.y = ((unsigned)__half_as_ushort(l[3]) << 16) | __half_as_ushort(l[2]);
        *(uint2*)(g_Ahi + dbase + e4 * 4) = uh;
        *(uint2*)(g_Alo + dbase + e4 * 4) = ul;
    }
}

// ---------------------------------------------------------------------------
// K2: split-fp16 mma.sync GEMM (hh + lh + hl), row-max epilogue -> atomicMax
// grid (32, 8, BDIM), block 256 (8 warps, 2x4, warp tile 64x32)
// 2-stage cp.async pipeline, 80KB smem -> 2 CTAs/SM
// ---------------------------------------------------------------------------
__global__ void __launch_bounds__(256, 2)
score_gemm(const float* __restrict__ bias) {
    int b = blockIdx.z;
    int nk = g_nkeep[b];
    int m0 = blockIdx.x * BM;
    if (m0 >= nk) return;
    int n0 = blockIdx.y * BN;

    extern __shared__ __align__(128) char sm[];
    uint32_t sb = smem_u32(sm);
    float* biasS = (float*)(sm + 2 * STAGE_BYTES);

    int tid = threadIdx.x, wid = tid >> 5, lane = tid & 31;
    if (tid < BN) biasS[tid] = bias[n0 + tid];

    const __half* gah = g_Ahi + (size_t)(b * SDIM + m0) * HDIM;
    const __half* gal = g_Alo + (size_t)(b * SDIM + m0) * HDIM;
    const __half* gbh = g_Bhi + (size_t)n0 * HDIM;
    const __half* gbl = g_Blo + (size_t)n0 * HDIM;

#define LOAD_STAGE(s, k0)                                                     \
    do {                                                                      \
        uint32_t st_ = sb + (s) * STAGE_BYTES;                                \
        _Pragma("unroll")                                                     \
        for (int i_ = 0; i_ < 2; i_++) {                                      \
            int cid_ = tid + i_ * 256;                                        \
            int r_ = cid_ >> 2, c_ = cid_ & 3;                                \
            uint32_t so_ = (uint32_t)(r_ * ROWB + c_ * 16);                   \
            size_t go_ = (size_t)r_ * HDIM + (k0) + c_ * 8;                   \
            CP16(st_ + so_,             gah + go_);                           \
            CP16(st_ + PLANE + so_,     gal + go_);                           \
            CP16(st_ + 2 * PLANE + so_, gbh + go_);                           \
            CP16(st_ + 3 * PLANE + so_, gbl + go_);                           \
        }                                                                     \
    } while (0)

    LOAD_STAGE(0, 0);
    CP_COMMIT();
    LOAD_STAGE(1, BKH);
    CP_COMMIT();

    int wm = wid >> 2, wn = wid & 3;
    float acc[4][4][4];
#pragma unroll
    for (int mt = 0; mt < 4; mt++)
#pragma unroll
        for (int nt = 0; nt < 4; nt++)
#pragma unroll
            for (int e = 0; e < 4; e++) acc[mt][nt][e] = 0.0f;

    uint32_t arow = (uint32_t)(wm * 64 + (lane & 15));
    uint32_t brow = (uint32_t)(wn * 32 + (lane & 15));
    uint32_t kcol = (uint32_t)((lane >> 4) * 16);

    for (int kt = 0; kt < KT; kt++) {
        CP_WAIT1();
        __syncthreads();

        uint32_t st = sb + (kt & 1) * STAGE_BYTES;
#pragma unroll
        for (int ks = 0; ks < 2; ks++) {
            uint32_t koff = (uint32_t)(ks * 32) + kcol;
            uint32_t bh[2][4], bl[2][4];
#pragma unroll
            for (int g = 0; g < 2; g++) {
                uint32_t rb = st + 2 * PLANE + (brow + g * 16) * ROWB + koff;
                LDX4(bh[g], rb);
                LDX4(bl[g], rb + PLANE);
            }
#pragma unroll
            for (int mt = 0; mt < 4; mt++) {
                uint32_t ah[4], al[4];
                uint32_t ra = st + (arow + mt * 16) * ROWB + koff;
                LDX4(ah, ra);
                LDX4(al, ra + PLANE);
#pragma unroll
                for (int nt = 0; nt < 4; nt++) {
                    int g = nt >> 1, s2 = nt & 1;
                    MMA16816(acc[mt][nt], ah, bh[g][s2], bh[g][s2 + 2]);
                    MMA16816(acc[mt][nt], al, bh[g][s2], bh[g][s2 + 2]);
                    MMA16816(acc[mt][nt], ah, bl[g][s2], bl[g][s2 + 2]);
                }
            }
        }
        __syncthreads();
        if (kt + 2 < KT) LOAD_STAGE(kt & 1, (kt + 2) * BKH);
        CP_COMMIT();
    }

    // ---- epilogue: bias add + row max + lane reduce + atomicMax ----
    float rmax[4][2];
#pragma unroll
    for (int mt = 0; mt < 4; mt++) { rmax[mt][0] = -3.4e38f; rmax[mt][1] = -3.4e38f; }
#pragma unroll
    for (int mt = 0; mt < 4; mt++)
#pragma unroll
        for (int nt = 0; nt < 4; nt++) {
            int cb = wn * 32 + nt * 8 + (lane & 3) * 2;
            float b0 = biasS[cb], b1 = biasS[cb + 1];
            rmax[mt][0] = fmaxf(rmax[mt][0], fmaxf(acc[mt][nt][0] + b0, acc[mt][nt][1] + b1));
            rmax[mt][1] = fmaxf(rmax[mt][1], fmaxf(acc[mt][nt][2] + b0, acc[mt][nt][3] + b1));
        }
#pragma unroll
    for (int off = 1; off <= 2; off <<= 1)
#pragma unroll
        for (int mt = 0; mt < 4; mt++) {
            rmax[mt][0] = fmaxf(rmax[mt][0], __shfl_xor_sync(0xFFFFFFFFu, rmax[mt][0], off));
            rmax[mt][1] = fmaxf(rmax[mt][1], __shfl_xor_sync(0xFFFFFFFFu, rmax[mt][1], off));
        }
    if ((lane & 3) == 0) {
#pragma unroll
        for (int mt = 0; mt < 4; mt++)
#pragma unroll
            for (int h2 = 0; h2 < 2; h2++) {
                int m = m0 + wm * 64 + mt * 16 + (lane >> 2) + h2 * 8;
                if (m < nk) {
                    int pos = g_tokpos[b * SDIM + m];
                    atomicMax(&g_score[b * SDIM + pos], mono(rmax[mt][h2]));
                }
            }
    }
#undef LOAD_STAGE
}

// ---------------------------------------------------------------------------
// K3: per-row top-T via bitonic sort of rebuilt keys -> new_mask
// ---------------------------------------------------------------------------
__device__ __forceinline__ unsigned long long make_key(int base, int i,
                                                       const float* pmask,
                                                       const float* amask) {
    if (pmask[base + i] <= 0.5f) return 0ull;
    unsigned u = g_score[base + i];
    unsigned bits = (u & 0x80000000u) ? (u & 0x7FFFFFFFu) : ~u;   // un-map
    float sc = __uint_as_float(bits);
    float a = amask[base + i];
    sc = sc + a * 100.0f + a;
    unsigned v = __float_as_uint(sc);
    v = (v & 0x80000000u) ? ~v : (v | 0x80000000u);               // re-map
    return ((unsigned long long)v << 32) | (unsigned long long)(0xFFFFFFFFu - (unsigned)i);
}

__global__ void select_kernel(const float* __restrict__ pmask,
                              const float* __restrict__ amask,
                              float* __restrict__ outmask) {
    int b = blockIdx.x;
    int t = threadIdx.x;
    __shared__ unsigned long long s[SDIM];
    int base = b * SDIM;

    for (int i = t; i < SDIM; i += 1024) s[i] = make_key(base, i, pmask, amask);
    __syncthreads();

    for (int k = 2; k <= SDIM; k <<= 1) {
        for (int j = k >> 1; j > 0; j >>= 1) {
            for (int i = t; i < SDIM; i += 1024) {
                int ixj = i ^ j;
                if (ixj > i) {
                    unsigned long long A = s[i], B = s[ixj];
                    bool up = ((i & k) == 0);
                    if ((A > B) == up) { s[i] = B; s[ixj] = A; }
                }
            }
            __syncthreads();
        }
    }

    int cz = g_nzero[b];
    int T = (int)((float)cz * 0.8f);
    if (T < 1) T = 1;
    unsigned long long thresh = s[SDIM - T];

    for (int i = t; i < SDIM; i += 1024)
        outmask[base + i] = (make_key(base, i, pmask, amask) >= thresh) ? 1.0f : 0.0f;
}

// ---------------------------------------------------------------------------
extern "C" void kernel_launch(void* const* d_in, const int* in_sizes, int n_in,
                              void* d_out, int out_size) {
    const float* hidden = (const float*)d_in[0];
    const float* amask  = (const float*)d_in[1];
    const float* pmask  = (const float*)d_in[2];
    const float* W      = (const float*)d_in[3];
    const float* bias   = (const float*)d_in[4];
    float* out = (float*)d_out;

    const int nh = BDIM * SDIM * HDIM;
    float* out_ret  = out;
    float* out_mask = out + nh;

    cudaFuncSetAttribute(score_gemm, cudaFuncAttributeMaxDynamicSharedMemorySize, SMEM_DYN);

    // compaction + counts + score/slot reset
    compact_kernel<<<BDIM, 1024>>>(pmask, amask);

    // W -> [n][k] fp16 hi/lo
    prep_w<<<dim3(32, 32), dim3(32, 8)>>>(W);

    // single pass: copy hidden -> out_ret, split kept rows into planes
    prep_copy<<<BDIM * SDIM, 128>>>((const float4*)hidden, (float4*)out_ret);

    // split-fp16 tensor-core score GEMM
    score_gemm<<<dim3(SDIM / BM, HDIM / BN, BDIM), 256, SMEM_DYN>>>(bias);

    // top-T selection per row
    select_kernel<<<BDIM, 1024>>>(pmask, amask, out_mask);
}